// round 1
// baseline (speedup 1.0000x reference)
#include <cuda_runtime.h>
#include <math.h>

#define NN 100000
#define EE 1000000
#define HIDD 64
#define EMBD 30

// ---------------- scratch (static device memory; no allocs) ----------------
__device__ float g_z1[NN * 64];
__device__ float g_out1[NN * 64];
__device__ float g_el1[NN], g_er1[NN], g_den1[NN];
__device__ float g_p1[EE];
__device__ float g_z2[NN * 32];      // 30 used + 2 pad (zero)
__device__ float g_out2[NN * 32];
__device__ float g_el2[NN], g_er2[NN], g_den2[NN];
__device__ float g_p2[EE];
__device__ float g_himg[EMBD];
__device__ float g_wa1[3], g_wr1[3];
__device__ float g_wa2[64], g_wr2[64];
__device__ float g_W2T[EMBD * 64];   // W2T[j*64+k] = W2[k*60+j]  (head-0 slice, transposed)
__device__ float g_acc[32];

// ---------------- K0: tiny prep ----------------
__global__ void k0_prep(const float* __restrict__ x, const float* __restrict__ W_lin1,
                        const float* __restrict__ w_conv2, const float* __restrict__ w_conv3,
                        const float* __restrict__ W1, const float* __restrict__ al1,
                        const float* __restrict__ ar1,
                        const float* __restrict__ W2, const float* __restrict__ al2,
                        const float* __restrict__ ar2)
{
    __shared__ float s_hi[EMBD];
    int t = threadIdx.x;  // 128 threads
    if (t < EMBD) {
        float acc = 0.f;
        const float* row = W_lin1 + t * 512;
        for (int k = 0; k < 512; k++) acc += row[k] * x[k];
        s_hi[t] = acc;
    }
    __syncthreads();
    if (t < EMBD) {
        float hi = s_hi[t];
        float acc = 0.f;
        for (int k = 0; k < 64; k++) {
            float s = 1.f / (1.f + __expf(-w_conv2[k] * hi));
            acc += w_conv3[k] * s;
        }
        g_himg[t] = 1.f / (1.f + __expf(-acc));
    }
    if (t < 3) {
        float a = 0.f, r = 0.f;
        for (int j = 0; j < 64; j++) { a += W1[t * 128 + j] * al1[j]; r += W1[t * 128 + j] * ar1[j]; }
        g_wa1[t] = a; g_wr1[t] = r;
    }
    if (t >= 64 && t < 128) {
        int k = t - 64;
        float a = 0.f, r = 0.f;
        for (int j = 0; j < EMBD; j++) { a += W2[k * 60 + j] * al2[j]; r += W2[k * 60 + j] * ar2[j]; }
        g_wa2[k] = a; g_wr2[k] = r;
    }
    for (int idx = t; idx < EMBD * 64; idx += 128) {
        int j = idx >> 6, k = idx & 63;
        g_W2T[idx] = W2[k * 60 + j];
    }
    if (t < 32) g_acc[t] = 0.f;
}

// ---------------- K1: layer-1 node features (head 0 only) ----------------
__global__ void k1_nodes1(const float* __restrict__ feat, const float* __restrict__ W1)
{
    int t = blockIdx.x * blockDim.x + threadIdx.x;
    if (t >= NN * 16) return;
    int n = t >> 4, q = t & 15;
    float f0 = feat[n * 3 + 0], f1 = feat[n * 3 + 1], f2 = feat[n * 3 + 2];
    int j = q * 4;
    float4 z;
    z.x = f0 * W1[j + 0] + f1 * W1[128 + j + 0] + f2 * W1[256 + j + 0];
    z.y = f0 * W1[j + 1] + f1 * W1[128 + j + 1] + f2 * W1[256 + j + 1];
    z.z = f0 * W1[j + 2] + f1 * W1[128 + j + 2] + f2 * W1[256 + j + 2];
    z.w = f0 * W1[j + 3] + f1 * W1[128 + j + 3] + f2 * W1[256 + j + 3];
    *(float4*)&g_z1[n * 64 + j] = z;
    *(float4*)&g_out1[n * 64 + j] = make_float4(0.f, 0.f, 0.f, 0.f);
    if (q == 0) {
        g_el1[n] = f0 * g_wa1[0] + f1 * g_wa1[1] + f2 * g_wa1[2];
        g_er1[n] = f0 * g_wr1[0] + f1 * g_wr1[1] + f2 * g_wr1[2];
        g_den1[n] = 0.f;
    }
}

// ---------------- K2 / K5: edge pass A (exp + denominator) ----------------
__global__ void k2_edge1a(const int* __restrict__ src, const int* __restrict__ dst)
{
    int i = blockIdx.x * blockDim.x + threadIdx.x;
    if (i >= EE) return;
    int s = src[i], d = dst[i];
    float e = g_el1[s] + g_er1[d];
    e = e > 0.f ? e : 0.2f * e;
    float p = __expf(e);
    g_p1[i] = p;
    atomicAdd(&g_den1[d], p);
}

__global__ void k5_edge2a(const int* __restrict__ src, const int* __restrict__ dst)
{
    int i = blockIdx.x * blockDim.x + threadIdx.x;
    if (i >= EE) return;
    int s = src[i], d = dst[i];
    float e = g_el2[s] + g_er2[d];
    e = e > 0.f ? e : 0.2f * e;
    float p = __expf(e);
    g_p2[i] = p;
    atomicAdd(&g_den2[d], p);
}

// ---------------- K3: layer-1 aggregation, warp per edge ----------------
__global__ void k3_edge1b(const int* __restrict__ src, const int* __restrict__ dst)
{
    int w = (blockIdx.x * blockDim.x + threadIdx.x) >> 5;
    if (w >= EE) return;
    int lane = threadIdx.x & 31;
    int s = src[w], d = dst[w];
    float alpha = g_p1[w] / g_den1[d];
    float v0 = alpha * g_z1[s * 64 + lane];
    float v1 = alpha * g_z1[s * 64 + 32 + lane];
    atomicAdd(&g_out1[d * 64 + lane], v0);
    atomicAdd(&g_out1[d * 64 + 32 + lane], v1);
}

// ---------------- K4: relu+bias, z2 = r1h0 @ W2[:, :30], el2/er2, zero-init ----------------
__global__ void __launch_bounds__(256) k4_nodes2(const float* __restrict__ b1)
{
    __shared__ float sW[EMBD * 64 + 2 * 64];
    for (int idx = threadIdx.x; idx < EMBD * 64; idx += blockDim.x) sW[idx] = g_W2T[idx];
    for (int idx = threadIdx.x; idx < 64; idx += blockDim.x) {
        sW[EMBD * 64 + idx] = g_wa2[idx];
        sW[EMBD * 64 + 64 + idx] = g_wr2[idx];
    }
    __syncthreads();
    int n = blockIdx.x * blockDim.x + threadIdx.x;
    if (n >= NN) return;

    float acc[EMBD];
#pragma unroll
    for (int j = 0; j < EMBD; j++) acc[j] = 0.f;
    float el = 0.f, er = 0.f;

#pragma unroll
    for (int kc = 0; kc < 64; kc += 8) {
        float r[8];
#pragma unroll
        for (int u = 0; u < 8; u += 4) {
            float4 o = *(const float4*)&g_out1[n * 64 + kc + u];
            float v;
            v = o.x + b1[kc + u + 0]; r[u + 0] = v > 0.f ? v : 0.f;
            v = o.y + b1[kc + u + 1]; r[u + 1] = v > 0.f ? v : 0.f;
            v = o.z + b1[kc + u + 2]; r[u + 2] = v > 0.f ? v : 0.f;
            v = o.w + b1[kc + u + 3]; r[u + 3] = v > 0.f ? v : 0.f;
        }
#pragma unroll
        for (int j = 0; j < EMBD; j++) {
#pragma unroll
            for (int u = 0; u < 8; u++)
                acc[j] += r[u] * sW[j * 64 + kc + u];
        }
#pragma unroll
        for (int u = 0; u < 8; u++) {
            el += r[u] * sW[EMBD * 64 + kc + u];
            er += r[u] * sW[EMBD * 64 + 64 + kc + u];
        }
    }
#pragma unroll
    for (int j = 0; j < EMBD; j++) g_z2[n * 32 + j] = acc[j];
    g_z2[n * 32 + 30] = 0.f;
    g_z2[n * 32 + 31] = 0.f;
    g_el2[n] = el; g_er2[n] = er; g_den2[n] = 0.f;
#pragma unroll
    for (int j = 0; j < 32; j += 4)
        *(float4*)&g_out2[n * 32 + j] = make_float4(0.f, 0.f, 0.f, 0.f);
}

// ---------------- K6: layer-2 aggregation, warp per edge ----------------
__global__ void k6_edge2b(const int* __restrict__ src, const int* __restrict__ dst)
{
    int w = (blockIdx.x * blockDim.x + threadIdx.x) >> 5;
    if (w >= EE) return;
    int lane = threadIdx.x & 31;
    int s = src[w], d = dst[w];
    float alpha = g_p2[w] / g_den2[d];
    float v = alpha * g_z2[s * 32 + lane];
    if (lane < 30) atomicAdd(&g_out2[d * 32 + lane], v);
}

// ---------------- K7: mean over nodes ----------------
__global__ void k7_reduce()
{
    int g = blockIdx.x * blockDim.x + threadIdx.x;  // 32768 threads
    int j = g & 31, r = g >> 5;
    float s = 0.f;
    for (int n = r; n < NN; n += 1024)
        s += g_out2[n * 32 + j];
    if (j < 30) atomicAdd(&g_acc[j], s);
}

// ---------------- K8: concat + linear + log_softmax ----------------
__global__ void k8_final(const float* __restrict__ vocab, const float* __restrict__ W_lin4,
                         const float* __restrict__ b2, float* __restrict__ out)
{
    __shared__ float h[70];
    __shared__ float l[2];
    int t = threadIdx.x;  // 96 threads
    if (t < 30)      h[t] = g_acc[t] * (1.f / (float)NN) + b2[t];
    else if (t < 60) h[t] = g_himg[t - 30];
    else if (t < 70) h[t] = vocab[t - 60];
    __syncthreads();
    if (t < 2) {
        float acc = 0.f;
        for (int k = 0; k < 70; k++) acc += W_lin4[t * 70 + k] * h[k];
        l[t] = acc;
    }
    __syncthreads();
    if (t < 2) {
        float m = fmaxf(l[0], l[1]);
        float lse = m + logf(expf(l[0] - m) + expf(l[1] - m));
        out[t] = l[t] - lse;
    }
}

// ---------------- launch ----------------
extern "C" void kernel_launch(void* const* d_in, const int* in_sizes, int n_in,
                              void* d_out, int out_size)
{
    const float* x       = (const float*)d_in[0];
    const float* feat    = (const float*)d_in[1];
    const float* vocab   = (const float*)d_in[2];
    const int*   src     = (const int*)d_in[3];
    const int*   dst     = (const int*)d_in[4];
    const float* W_lin1  = (const float*)d_in[5];
    const float* w_conv2 = (const float*)d_in[6];
    const float* w_conv3 = (const float*)d_in[7];
    const float* W_lin4  = (const float*)d_in[8];
    const float* W1      = (const float*)d_in[9];
    const float* al1     = (const float*)d_in[10];
    const float* ar1     = (const float*)d_in[11];
    const float* b1      = (const float*)d_in[12];
    const float* W2      = (const float*)d_in[13];
    const float* al2     = (const float*)d_in[14];
    const float* ar2     = (const float*)d_in[15];
    const float* b2      = (const float*)d_in[16];
    float* out = (float*)d_out;

    k0_prep<<<1, 128>>>(x, W_lin1, w_conv2, w_conv3, W1, al1, ar1, W2, al2, ar2);
    k1_nodes1<<<(NN * 16 + 255) / 256, 256>>>(feat, W1);
    k2_edge1a<<<(EE + 255) / 256, 256>>>(src, dst);
    k3_edge1b<<<(EE * 32 + 255) / 256, 256>>>(src, dst);
    k4_nodes2<<<(NN + 255) / 256, 256>>>(b1);
    k5_edge2a<<<(EE + 255) / 256, 256>>>(src, dst);
    k6_edge2b<<<(EE * 32 + 255) / 256, 256>>>(src, dst);
    k7_reduce<<<128, 256>>>();
    k8_final<<<1, 96>>>(vocab, W_lin4, b2, out);
}

// round 4
// speedup vs baseline: 1.6249x; 1.6249x over previous
#include <cuda_runtime.h>
#include <math.h>

#define NN 100000
#define EE 1000000
#define EMBD 30

// ---------------- scratch (static device memory; no allocs) ----------------
__device__ float g_z1[NN * 64];
__device__ float g_out1[NN * 64];
__device__ float g_el1[NN], g_er1[NN];
__device__ float g_z2[NN * 32];      // 30 used + 2 pad (zero)
__device__ float g_out2[NN * 32];
__device__ float g_el2[NN], g_er2[NN];
__device__ float g_himg[EMBD];
__device__ float g_wa1[3], g_wr1[3];
__device__ float g_wa2[64], g_wr2[64];
__device__ float g_W2T[EMBD * 64];   // W2T[j*64+k] = W2[k*60+j]  (head-0 slice, transposed)
__device__ float g_acc[32];

// CSR build scratch
__device__ int g_count[NN];
__device__ int g_start[NN + 1];
__device__ int g_cursor[NN];
__device__ int g_bsum[256];
__device__ int g_boff[256];
__device__ int g_srcs[EE];           // src node id per dst-sorted edge

// ---------------- K0: tiny prep ----------------
__global__ void k0_prep(const float* __restrict__ x, const float* __restrict__ W_lin1,
                        const float* __restrict__ w_conv2, const float* __restrict__ w_conv3,
                        const float* __restrict__ W1, const float* __restrict__ al1,
                        const float* __restrict__ ar1,
                        const float* __restrict__ W2, const float* __restrict__ al2,
                        const float* __restrict__ ar2)
{
    __shared__ float s_hi[EMBD];
    int t = threadIdx.x;  // 128 threads
    if (t < EMBD) {
        float acc = 0.f;
        const float* row = W_lin1 + t * 512;
        for (int k = 0; k < 512; k++) acc += row[k] * x[k];
        s_hi[t] = acc;
    }
    __syncthreads();
    if (t < EMBD) {
        float hi = s_hi[t];
        float acc = 0.f;
        for (int k = 0; k < 64; k++) {
            float s = 1.f / (1.f + __expf(-w_conv2[k] * hi));
            acc += w_conv3[k] * s;
        }
        g_himg[t] = 1.f / (1.f + __expf(-acc));
    }
    if (t < 3) {
        float a = 0.f, r = 0.f;
        for (int j = 0; j < 64; j++) { a += W1[t * 128 + j] * al1[j]; r += W1[t * 128 + j] * ar1[j]; }
        g_wa1[t] = a; g_wr1[t] = r;
    }
    if (t >= 64 && t < 128) {
        int k = t - 64;
        float a = 0.f, r = 0.f;
        for (int j = 0; j < EMBD; j++) { a += W2[k * 60 + j] * al2[j]; r += W2[k * 60 + j] * ar2[j]; }
        g_wa2[k] = a; g_wr2[k] = r;
    }
    for (int idx = t; idx < EMBD * 64; idx += 128) {
        int j = idx >> 6, k = idx & 63;
        g_W2T[idx] = W2[k * 60 + j];
    }
    if (t < 32) g_acc[t] = 0.f;
}

// ---------------- K1: layer-1 node features (head 0 only) + zero histogram ----------------
__global__ void k1_nodes1(const float* __restrict__ feat, const float* __restrict__ W1)
{
    int t = blockIdx.x * blockDim.x + threadIdx.x;
    if (t >= NN * 16) return;
    int n = t >> 4, q = t & 15;
    float f0 = feat[n * 3 + 0], f1 = feat[n * 3 + 1], f2 = feat[n * 3 + 2];
    int j = q * 4;
    float4 z;
    z.x = f0 * W1[j + 0] + f1 * W1[128 + j + 0] + f2 * W1[256 + j + 0];
    z.y = f0 * W1[j + 1] + f1 * W1[128 + j + 1] + f2 * W1[256 + j + 1];
    z.z = f0 * W1[j + 2] + f1 * W1[128 + j + 2] + f2 * W1[256 + j + 2];
    z.w = f0 * W1[j + 3] + f1 * W1[128 + j + 3] + f2 * W1[256 + j + 3];
    *(float4*)&g_z1[n * 64 + j] = z;
    if (q == 0) {
        g_el1[n] = f0 * g_wa1[0] + f1 * g_wa1[1] + f2 * g_wa1[2];
        g_er1[n] = f0 * g_wr1[0] + f1 * g_wr1[1] + f2 * g_wr1[2];
        g_count[n] = 0;
    }
}

// ---------------- CSR build ----------------
__global__ void kh_hist(const int* __restrict__ dst)
{
    int i = blockIdx.x * blockDim.x + threadIdx.x;
    if (i >= EE) return;
    atomicAdd(&g_count[dst[i]], 1);
}

// block-level exclusive scan, 512 elems per block
__global__ void ks1_scan(void)
{
    __shared__ int sm[512];
    int t = threadIdx.x;
    int i = blockIdx.x * 512 + t;
    int v = (i < NN) ? g_count[i] : 0;
    sm[t] = v;
    __syncthreads();
#pragma unroll
    for (int off = 1; off < 512; off <<= 1) {
        int u = (t >= off) ? sm[t - off] : 0;
        __syncthreads();
        sm[t] += u;
        __syncthreads();
    }
    if (i < NN) g_start[i] = sm[t] - v;   // exclusive within block
    if (t == 511) g_bsum[blockIdx.x] = sm[511];
}

__global__ void ks2_scan(void)   // 1 block, 256 threads, 196 valid block sums
{
    __shared__ int sm[256];
    int t = threadIdx.x;
    int v = (t < 196) ? g_bsum[t] : 0;
    sm[t] = v;
    __syncthreads();
#pragma unroll
    for (int off = 1; off < 256; off <<= 1) {
        int u = (t >= off) ? sm[t - off] : 0;
        __syncthreads();
        sm[t] += u;
        __syncthreads();
    }
    if (t < 196) g_boff[t] = sm[t] - v;
}

__global__ void ks3_apply(void)
{
    int i = blockIdx.x * blockDim.x + threadIdx.x;
    if (i < NN) {
        int st = g_start[i] + g_boff[i >> 9];
        g_start[i] = st;
        g_cursor[i] = st;
    }
    if (i == NN) g_start[NN] = EE;
}

__global__ void kd_scatter(const int* __restrict__ src, const int* __restrict__ dst)
{
    int i = blockIdx.x * blockDim.x + threadIdx.x;
    if (i >= EE) return;
    int d = dst[i];
    int pos = atomicAdd(&g_cursor[d], 1);
    g_srcs[pos] = src[i];
}

// ---------------- K3: layer-1 aggregation, warp per dst node, NO atomics ----------------
__global__ void __launch_bounds__(256) k3_agg1(void)
{
    int warp = (blockIdx.x * 256 + threadIdx.x) >> 5;
    if (warp >= NN) return;
    int lane = threadIdx.x & 31;
    int n = warp;
    int rs = g_start[n], re = g_start[n + 1];
    float ern = g_er1[n];

    // phase A: softmax denominator (warp-reduced, no atomics)
    float den = 0.f;
    for (int e = rs + lane; e < re; e += 32) {
        int s = g_srcs[e];
        float v = g_el1[s] + ern;
        v = v > 0.f ? v : 0.2f * v;
        den += __expf(v);
    }
#pragma unroll
    for (int o = 16; o > 0; o >>= 1) den += __shfl_xor_sync(0xffffffffu, den, o);
    float inv = (re > rs) ? (1.f / den) : 0.f;

    // phase B: weighted gather-accumulate in registers
    float a0 = 0.f, a1 = 0.f;
    for (int base = rs; base < re; base += 32) {
        int m = re - base; if (m > 32) m = 32;
        int   s_l = 0;
        float p_l = 0.f;
        if (lane < m) {
            s_l = g_srcs[base + lane];
            float v = g_el1[s_l] + ern;
            v = v > 0.f ? v : 0.2f * v;
            p_l = __expf(v);
        }
        for (int j = 0; j < m; j++) {
            int   s     = __shfl_sync(0xffffffffu, s_l, j);
            float alpha = __shfl_sync(0xffffffffu, p_l, j) * inv;
            a0 = fmaf(alpha, g_z1[s * 64 + lane], a0);
            a1 = fmaf(alpha, g_z1[s * 64 + 32 + lane], a1);
        }
    }
    g_out1[n * 64 + lane]      = a0;
    g_out1[n * 64 + 32 + lane] = a1;
}

// ---------------- K4: relu+bias, z2 = r1h0 @ W2[:, :30], el2/er2 ----------------
__global__ void __launch_bounds__(256) k4_nodes2(const float* __restrict__ b1)
{
    __shared__ float sW[EMBD * 64 + 2 * 64];
    for (int idx = threadIdx.x; idx < EMBD * 64; idx += blockDim.x) sW[idx] = g_W2T[idx];
    for (int idx = threadIdx.x; idx < 64; idx += blockDim.x) {
        sW[EMBD * 64 + idx] = g_wa2[idx];
        sW[EMBD * 64 + 64 + idx] = g_wr2[idx];
    }
    __syncthreads();
    int n = blockIdx.x * blockDim.x + threadIdx.x;
    if (n >= NN) return;

    float acc[EMBD];
#pragma unroll
    for (int j = 0; j < EMBD; j++) acc[j] = 0.f;
    float el = 0.f, er = 0.f;

#pragma unroll
    for (int kc = 0; kc < 64; kc += 8) {
        float r[8];
#pragma unroll
        for (int u = 0; u < 8; u += 4) {
            float4 o = *(const float4*)&g_out1[n * 64 + kc + u];
            float v;
            v = o.x + b1[kc + u + 0]; r[u + 0] = v > 0.f ? v : 0.f;
            v = o.y + b1[kc + u + 1]; r[u + 1] = v > 0.f ? v : 0.f;
            v = o.z + b1[kc + u + 2]; r[u + 2] = v > 0.f ? v : 0.f;
            v = o.w + b1[kc + u + 3]; r[u + 3] = v > 0.f ? v : 0.f;
        }
#pragma unroll
        for (int j = 0; j < EMBD; j++) {
#pragma unroll
            for (int u = 0; u < 8; u++)
                acc[j] += r[u] * sW[j * 64 + kc + u];
        }
#pragma unroll
        for (int u = 0; u < 8; u++) {
            el += r[u] * sW[EMBD * 64 + kc + u];
            er += r[u] * sW[EMBD * 64 + 64 + kc + u];
        }
    }
#pragma unroll
    for (int j = 0; j < EMBD; j++) g_z2[n * 32 + j] = acc[j];
    g_z2[n * 32 + 30] = 0.f;
    g_z2[n * 32 + 31] = 0.f;
    g_el2[n] = el; g_er2[n] = er;
}

// ---------------- K6: layer-2 aggregation, warp per dst node ----------------
__global__ void __launch_bounds__(256) k6_agg2(void)
{
    int warp = (blockIdx.x * 256 + threadIdx.x) >> 5;
    if (warp >= NN) return;
    int lane = threadIdx.x & 31;
    int n = warp;
    int rs = g_start[n], re = g_start[n + 1];
    float ern = g_er2[n];

    float den = 0.f;
    for (int e = rs + lane; e < re; e += 32) {
        int s = g_srcs[e];
        float v = g_el2[s] + ern;
        v = v > 0.f ? v : 0.2f * v;
        den += __expf(v);
    }
#pragma unroll
    for (int o = 16; o > 0; o >>= 1) den += __shfl_xor_sync(0xffffffffu, den, o);
    float inv = (re > rs) ? (1.f / den) : 0.f;

    float a0 = 0.f;
    for (int base = rs; base < re; base += 32) {
        int m = re - base; if (m > 32) m = 32;
        int   s_l = 0;
        float p_l = 0.f;
        if (lane < m) {
            s_l = g_srcs[base + lane];
            float v = g_el2[s_l] + ern;
            v = v > 0.f ? v : 0.2f * v;
            p_l = __expf(v);
        }
        for (int j = 0; j < m; j++) {
            int   s     = __shfl_sync(0xffffffffu, s_l, j);
            float alpha = __shfl_sync(0xffffffffu, p_l, j) * inv;
            a0 = fmaf(alpha, g_z2[s * 32 + lane], a0);
        }
    }
    g_out2[n * 32 + lane] = a0;   // lanes 30/31 write 0 (z2 padded with zeros)
}

// ---------------- K7: mean over nodes ----------------
__global__ void k7_reduce(void)
{
    int g = blockIdx.x * blockDim.x + threadIdx.x;  // 32768 threads
    int j = g & 31, r = g >> 5;
    float s = 0.f;
    for (int n = r; n < NN; n += 1024)
        s += g_out2[n * 32 + j];
    if (j < 30) atomicAdd(&g_acc[j], s);
}

// ---------------- K8: concat + linear + log_softmax ----------------
__global__ void k8_final(const float* __restrict__ vocab, const float* __restrict__ W_lin4,
                         const float* __restrict__ b2, float* __restrict__ out)
{
    __shared__ float h[70];
    __shared__ float l[2];
    int t = threadIdx.x;  // 96 threads
    if (t < 30)      h[t] = g_acc[t] * (1.f / (float)NN) + b2[t];
    else if (t < 60) h[t] = g_himg[t - 30];
    else if (t < 70) h[t] = vocab[t - 60];
    __syncthreads();
    if (t < 2) {
        float acc = 0.f;
        for (int k = 0; k < 70; k++) acc += W_lin4[t * 70 + k] * h[k];
        l[t] = acc;
    }
    __syncthreads();
    if (t < 2) {
        float m = fmaxf(l[0], l[1]);
        float lse = m + logf(expf(l[0] - m) + expf(l[1] - m));
        out[t] = l[t] - lse;
    }
}

// ---------------- launch ----------------
extern "C" void kernel_launch(void* const* d_in, const int* in_sizes, int n_in,
                              void* d_out, int out_size)
{
    const float* x       = (const float*)d_in[0];
    const float* feat    = (const float*)d_in[1];
    const float* vocab   = (const float*)d_in[2];
    const int*   src     = (const int*)d_in[3];
    const int*   dst     = (const int*)d_in[4];
    const float* W_lin1  = (const float*)d_in[5];
    const float* w_conv2 = (const float*)d_in[6];
    const float* w_conv3 = (const float*)d_in[7];
    const float* W_lin4  = (const float*)d_in[8];
    const float* W1      = (const float*)d_in[9];
    const float* al1     = (const float*)d_in[10];
    const float* ar1     = (const float*)d_in[11];
    const float* b1      = (const float*)d_in[12];
    const float* W2      = (const float*)d_in[13];
    const float* al2     = (const float*)d_in[14];
    const float* ar2     = (const float*)d_in[15];
    const float* b2      = (const float*)d_in[16];
    float* out = (float*)d_out;

    k0_prep<<<1, 128>>>(x, W_lin1, w_conv2, w_conv3, W1, al1, ar1, W2, al2, ar2);
    k1_nodes1<<<(NN * 16 + 255) / 256, 256>>>(feat, W1);
    kh_hist<<<(EE + 255) / 256, 256>>>(dst);
    ks1_scan<<<196, 512>>>();
    ks2_scan<<<1, 256>>>();
    ks3_apply<<<(NN + 1 + 255) / 256, 256>>>();
    kd_scatter<<<(EE + 255) / 256, 256>>>(src, dst);
    k3_agg1<<<(NN * 32 + 255) / 256, 256>>>();
    k4_nodes2<<<(NN + 255) / 256, 256>>>(b1);
    k6_agg2<<<(NN * 32 + 255) / 256, 256>>>();
    k7_reduce<<<128, 256>>>();
    k8_final<<<1, 96>>>(vocab, W_lin4, b2, out);
}

// round 5
// speedup vs baseline: 1.8538x; 1.1409x over previous
#include <cuda_runtime.h>
#include <cuda_fp16.h>
#include <math.h>

#define NN 100000
#define EE 1000000
#define EMBD 30

// ---------------- scratch (static device memory; no allocs) ----------------
__device__ __half g_z1h[NN * 64];     // layer-1 z, head 0, fp16
__device__ float  g_out1[NN * 64];
__device__ float  g_el1[NN], g_er1[NN];
__device__ __half g_z2h[NN * 32];     // 30 used + 2 zero pad, fp16
__device__ float  g_el2[NN], g_er2[NN];
__device__ float  g_himg[EMBD];
__device__ float  g_wa1[3], g_wr1[3];
__device__ float  g_wa2[64], g_wr2[64];
__device__ float  g_W2T[EMBD * 64];   // W2T[j*64+k] = W2[k*60+j]
__device__ float  g_acc[32];

// CSR build scratch
__device__ int   g_count[NN];
__device__ int   g_start[NN + 1];
__device__ int   g_cursor[NN];
__device__ int   g_bsum[256];
__device__ int   g_boff[256];
__device__ int   g_srcs[EE];          // src node id per dst-sorted edge
__device__ float g_p1[EE];            // exp(leaky(el1[s]+er1[d])) per dst-sorted edge

// ---------------- K0: tiny prep ----------------
__global__ void k0_prep(const float* __restrict__ x, const float* __restrict__ W_lin1,
                        const float* __restrict__ w_conv2, const float* __restrict__ w_conv3,
                        const float* __restrict__ W1, const float* __restrict__ al1,
                        const float* __restrict__ ar1,
                        const float* __restrict__ W2, const float* __restrict__ al2,
                        const float* __restrict__ ar2)
{
    __shared__ float s_hi[EMBD];
    int t = threadIdx.x;  // 128 threads
    if (t < EMBD) {
        float acc = 0.f;
        const float* row = W_lin1 + t * 512;
        for (int k = 0; k < 512; k++) acc += row[k] * x[k];
        s_hi[t] = acc;
    }
    __syncthreads();
    if (t < EMBD) {
        float hi = s_hi[t];
        float acc = 0.f;
        for (int k = 0; k < 64; k++) {
            float s = 1.f / (1.f + __expf(-w_conv2[k] * hi));
            acc += w_conv3[k] * s;
        }
        g_himg[t] = 1.f / (1.f + __expf(-acc));
    }
    if (t < 3) {
        float a = 0.f, r = 0.f;
        for (int j = 0; j < 64; j++) { a += W1[t * 128 + j] * al1[j]; r += W1[t * 128 + j] * ar1[j]; }
        g_wa1[t] = a; g_wr1[t] = r;
    }
    if (t >= 64 && t < 128) {
        int k = t - 64;
        float a = 0.f, r = 0.f;
        for (int j = 0; j < EMBD; j++) { a += W2[k * 60 + j] * al2[j]; r += W2[k * 60 + j] * ar2[j]; }
        g_wa2[k] = a; g_wr2[k] = r;
    }
    for (int idx = t; idx < EMBD * 64; idx += 128) {
        int j = idx >> 6, k = idx & 63;
        g_W2T[idx] = W2[k * 60 + j];
    }
    if (t < 32) g_acc[t] = 0.f;
}

// ---------------- K1: layer-1 node features (head 0, fp16) + zero histogram ----------------
__global__ void k1_nodes1(const float* __restrict__ feat, const float* __restrict__ W1)
{
    int t = blockIdx.x * blockDim.x + threadIdx.x;
    if (t >= NN * 8) return;
    int n = t >> 3, q = t & 7;
    float f0 = feat[n * 3 + 0], f1 = feat[n * 3 + 1], f2 = feat[n * 3 + 2];
    int j = q * 8;
    float z[8];
#pragma unroll
    for (int u = 0; u < 8; u++)
        z[u] = f0 * W1[j + u] + f1 * W1[128 + j + u] + f2 * W1[256 + j + u];
    union { __half2 h[4]; uint4 u4; } pk;
#pragma unroll
    for (int u = 0; u < 4; u++)
        pk.h[u] = __floats2half2_rn(z[2 * u], z[2 * u + 1]);
    *(uint4*)&g_z1h[n * 64 + j] = pk.u4;
    if (q == 0) {
        g_el1[n] = f0 * g_wa1[0] + f1 * g_wa1[1] + f2 * g_wa1[2];
        g_er1[n] = f0 * g_wr1[0] + f1 * g_wr1[1] + f2 * g_wr1[2];
        g_count[n] = 0;
    }
}

// ---------------- CSR build ----------------
__global__ void kh_hist(const int* __restrict__ dst)
{
    int i = blockIdx.x * blockDim.x + threadIdx.x;
    if (i >= EE) return;
    atomicAdd(&g_count[dst[i]], 1);
}

// shfl-based block exclusive scan, 512 elems per block
__global__ void ks1_scan(void)
{
    __shared__ int ws[16];
    int t = threadIdx.x, lane = t & 31, w = t >> 5;
    int i = blockIdx.x * 512 + t;
    int v = (i < NN) ? g_count[i] : 0;
    int x = v;
#pragma unroll
    for (int off = 1; off < 32; off <<= 1) {
        int u = __shfl_up_sync(0xffffffffu, x, off);
        if (lane >= off) x += u;
    }
    if (lane == 31) ws[w] = x;
    __syncthreads();
    if (w == 0) {
        int y = (lane < 16) ? ws[lane] : 0;
#pragma unroll
        for (int off = 1; off < 16; off <<= 1) {
            int u = __shfl_up_sync(0xffffffffu, y, off);
            if (lane >= off) y += u;
        }
        if (lane < 16) ws[lane] = y;
    }
    __syncthreads();
    int incl = x + (w > 0 ? ws[w - 1] : 0);
    if (i < NN) g_start[i] = incl - v;
    if (t == 511) g_bsum[blockIdx.x] = incl;
}

__global__ void ks2_scan(void)   // 1 block, 256 threads, 196 valid block sums
{
    __shared__ int ws[8];
    int t = threadIdx.x, lane = t & 31, w = t >> 5;
    int v = (t < 196) ? g_bsum[t] : 0;
    int x = v;
#pragma unroll
    for (int off = 1; off < 32; off <<= 1) {
        int u = __shfl_up_sync(0xffffffffu, x, off);
        if (lane >= off) x += u;
    }
    if (lane == 31) ws[w] = x;
    __syncthreads();
    if (w == 0) {
        int y = (lane < 8) ? ws[lane] : 0;
#pragma unroll
        for (int off = 1; off < 8; off <<= 1) {
            int u = __shfl_up_sync(0xffffffffu, y, off);
            if (lane >= off) y += u;
        }
        if (lane < 8) ws[lane] = y;
    }
    __syncthreads();
    int incl = x + (w > 0 ? ws[w - 1] : 0);
    if (t < 196) g_boff[t] = incl - v;
}

__global__ void ks3_apply(void)
{
    int i = blockIdx.x * blockDim.x + threadIdx.x;
    if (i < NN) {
        int st = g_start[i] + g_boff[i >> 9];
        g_start[i] = st;
        g_cursor[i] = st;
    }
    if (i == NN) g_start[NN] = EE;
}

// scatter + precompute layer-1 edge weight p1
__global__ void kd_scatter(const int* __restrict__ src, const int* __restrict__ dst)
{
    int i = blockIdx.x * blockDim.x + threadIdx.x;
    if (i >= EE) return;
    int s = src[i], d = dst[i];
    int pos = atomicAdd(&g_cursor[d], 1);
    float v = g_el1[s] + g_er1[d];
    v = v > 0.f ? v : 0.2f * v;
    g_srcs[pos] = s;
    g_p1[pos] = __expf(v);
}

// ---------------- K3: layer-1 aggregation, warp per dst node ----------------
__global__ void __launch_bounds__(256) k3_agg1(void)
{
    int warp = (blockIdx.x * 256 + threadIdx.x) >> 5;
    if (warp >= NN) return;
    int lane = threadIdx.x & 31;
    int n = warp;
    int rs = g_start[n], re = g_start[n + 1];

    // softmax denominator: coalesced segment sum of precomputed p
    float den = 0.f;
    for (int e = rs + lane; e < re; e += 32) den += g_p1[e];
#pragma unroll
    for (int o = 16; o > 0; o >>= 1) den += __shfl_xor_sync(0xffffffffu, den, o);
    float inv = (re > rs) ? (1.f / den) : 0.f;

    // weighted gather-accumulate: one 128B fp16 gather per edge
    const __half2* zz = (const __half2*)g_z1h;
    float a0 = 0.f, a1 = 0.f;
    for (int base = rs; base < re; base += 32) {
        int m = re - base; if (m > 32) m = 32;
        int   s_l = 0;
        float p_l = 0.f;
        if (lane < m) {
            s_l = g_srcs[base + lane];
            p_l = g_p1[base + lane];
        }
        for (int j = 0; j < m; j++) {
            int   s     = __shfl_sync(0xffffffffu, s_l, j);
            float alpha = __shfl_sync(0xffffffffu, p_l, j) * inv;
            float2 f = __half22float2(zz[s * 32 + lane]);
            a0 = fmaf(alpha, f.x, a0);
            a1 = fmaf(alpha, f.y, a1);
        }
    }
    *(float2*)&g_out1[n * 64 + 2 * lane] = make_float2(a0, a1);
}

// ---------------- K4: relu+bias, z2 = r1h0 @ W2[:, :30] (fp16 out), el2/er2 ----------------
__global__ void __launch_bounds__(256) k4_nodes2(const float* __restrict__ b1)
{
    __shared__ float sW[EMBD * 64 + 2 * 64];
    for (int idx = threadIdx.x; idx < EMBD * 64; idx += blockDim.x) sW[idx] = g_W2T[idx];
    for (int idx = threadIdx.x; idx < 64; idx += blockDim.x) {
        sW[EMBD * 64 + idx] = g_wa2[idx];
        sW[EMBD * 64 + 64 + idx] = g_wr2[idx];
    }
    __syncthreads();
    int n = blockIdx.x * blockDim.x + threadIdx.x;
    if (n >= NN) return;

    float acc[EMBD];
#pragma unroll
    for (int j = 0; j < EMBD; j++) acc[j] = 0.f;
    float el = 0.f, er = 0.f;

#pragma unroll
    for (int kc = 0; kc < 64; kc += 8) {
        float r[8];
#pragma unroll
        for (int u = 0; u < 8; u += 4) {
            float4 o = *(const float4*)&g_out1[n * 64 + kc + u];
            float v;
            v = o.x + b1[kc + u + 0]; r[u + 0] = v > 0.f ? v : 0.f;
            v = o.y + b1[kc + u + 1]; r[u + 1] = v > 0.f ? v : 0.f;
            v = o.z + b1[kc + u + 2]; r[u + 2] = v > 0.f ? v : 0.f;
            v = o.w + b1[kc + u + 3]; r[u + 3] = v > 0.f ? v : 0.f;
        }
#pragma unroll
        for (int j = 0; j < EMBD; j++) {
#pragma unroll
            for (int u = 0; u < 8; u++)
                acc[j] += r[u] * sW[j * 64 + kc + u];
        }
#pragma unroll
        for (int u = 0; u < 8; u++) {
            el += r[u] * sW[EMBD * 64 + kc + u];
            er += r[u] * sW[EMBD * 64 + 64 + kc + u];
        }
    }
    // pack 30 halves + 2 zero pads as 4x uint4
    union { __half2 h[16]; uint4 u4[4]; } pk;
#pragma unroll
    for (int j = 0; j < 15; j++) pk.h[j] = __floats2half2_rn(acc[2 * j], acc[2 * j + 1]);
    pk.h[15] = __floats2half2_rn(0.f, 0.f);
#pragma unroll
    for (int u = 0; u < 4; u++)
        *(uint4*)&g_z2h[n * 32 + u * 8] = pk.u4[u];
    g_el2[n] = el; g_er2[n] = er;
}

// ---------------- K6: layer-2 aggregation + block-level mean accumulation ----------------
__global__ void __launch_bounds__(256) k6_agg2(void)
{
    __shared__ float sacc[32];
    if (threadIdx.x < 32) sacc[threadIdx.x] = 0.f;
    __syncthreads();

    int warp = (blockIdx.x * 256 + threadIdx.x) >> 5;
    int lane = threadIdx.x & 31;
    int rs = 0, re = 0;
    float ern = 0.f;
    if (warp < NN) {
        rs = g_start[warp]; re = g_start[warp + 1];
        ern = g_er2[warp];
    }

    float a0 = 0.f;
    int deg = re - rs;
    if (deg > 0 && deg <= 32) {
        // fast path: single pass, p computed once
        int   s_l = 0;
        float p_l = 0.f;
        if (lane < deg) {
            s_l = g_srcs[rs + lane];
            float v = g_el2[s_l] + ern;
            v = v > 0.f ? v : 0.2f * v;
            p_l = __expf(v);
        }
        float den = p_l;
#pragma unroll
        for (int o = 16; o > 0; o >>= 1) den += __shfl_xor_sync(0xffffffffu, den, o);
        float inv = 1.f / den;
        for (int j = 0; j < deg; j++) {
            int   s     = __shfl_sync(0xffffffffu, s_l, j);
            float alpha = __shfl_sync(0xffffffffu, p_l, j) * inv;
            a0 = fmaf(alpha, __half2float(g_z2h[s * 32 + lane]), a0);
        }
    } else if (deg > 32) {
        float den = 0.f;
        for (int e = rs + lane; e < re; e += 32) {
            int s = g_srcs[e];
            float v = g_el2[s] + ern;
            v = v > 0.f ? v : 0.2f * v;
            den += __expf(v);
        }
#pragma unroll
        for (int o = 16; o > 0; o >>= 1) den += __shfl_xor_sync(0xffffffffu, den, o);
        float inv = 1.f / den;
        for (int base = rs; base < re; base += 32) {
            int m = re - base; if (m > 32) m = 32;
            int   s_l = 0;
            float p_l = 0.f;
            if (lane < m) {
                s_l = g_srcs[base + lane];
                float v = g_el2[s_l] + ern;
                v = v > 0.f ? v : 0.2f * v;
                p_l = __expf(v);
            }
            for (int j = 0; j < m; j++) {
                int   s     = __shfl_sync(0xffffffffu, s_l, j);
                float alpha = __shfl_sync(0xffffffffu, p_l, j) * inv;
                a0 = fmaf(alpha, __half2float(g_z2h[s * 32 + lane]), a0);
            }
        }
    }

    // block-level accumulation of node sums (mean over nodes is all we need)
    atomicAdd(&sacc[lane], a0);
    __syncthreads();
    if (threadIdx.x < 30)
        atomicAdd(&g_acc[threadIdx.x], sacc[threadIdx.x]);
}

// ---------------- K8: concat + linear + log_softmax ----------------
__global__ void k8_final(const float* __restrict__ vocab, const float* __restrict__ W_lin4,
                         const float* __restrict__ b2, float* __restrict__ out)
{
    __shared__ float h[70];
    __shared__ float l[2];
    int t = threadIdx.x;  // 96 threads
    if (t < 30)      h[t] = g_acc[t] * (1.f / (float)NN) + b2[t];
    else if (t < 60) h[t] = g_himg[t - 30];
    else if (t < 70) h[t] = vocab[t - 60];
    __syncthreads();
    if (t < 2) {
        float acc = 0.f;
        for (int k = 0; k < 70; k++) acc += W_lin4[t * 70 + k] * h[k];
        l[t] = acc;
    }
    __syncthreads();
    if (t < 2) {
        float m = fmaxf(l[0], l[1]);
        float lse = m + logf(expf(l[0] - m) + expf(l[1] - m));
        out[t] = l[t] - lse;
    }
}

// ---------------- launch ----------------
extern "C" void kernel_launch(void* const* d_in, const int* in_sizes, int n_in,
                              void* d_out, int out_size)
{
    const float* x       = (const float*)d_in[0];
    const float* feat    = (const float*)d_in[1];
    const float* vocab   = (const float*)d_in[2];
    const int*   src     = (const int*)d_in[3];
    const int*   dst     = (const int*)d_in[4];
    const float* W_lin1  = (const float*)d_in[5];
    const float* w_conv2 = (const float*)d_in[6];
    const float* w_conv3 = (const float*)d_in[7];
    const float* W_lin4  = (const float*)d_in[8];
    const float* W1      = (const float*)d_in[9];
    const float* al1     = (const float*)d_in[10];
    const float* ar1     = (const float*)d_in[11];
    const float* b1      = (const float*)d_in[12];
    const float* W2      = (const float*)d_in[13];
    const float* al2     = (const float*)d_in[14];
    const float* ar2     = (const float*)d_in[15];
    const float* b2      = (const float*)d_in[16];
    float* out = (float*)d_out;

    k0_prep<<<1, 128>>>(x, W_lin1, w_conv2, w_conv3, W1, al1, ar1, W2, al2, ar2);
    k1_nodes1<<<(NN * 8 + 255) / 256, 256>>>(feat, W1);
    kh_hist<<<(EE + 255) / 256, 256>>>(dst);
    ks1_scan<<<196, 512>>>();
    ks2_scan<<<1, 256>>>();
    ks3_apply<<<(NN + 1 + 255) / 256, 256>>>();
    kd_scatter<<<(EE + 255) / 256, 256>>>(src, dst);
    k3_agg1<<<(NN * 32 + 255) / 256, 256>>>();
    k4_nodes2<<<(NN + 255) / 256, 256>>>(b1);
    k6_agg2<<<(NN * 32 + 255) / 256, 256>>>();
    k8_final<<<1, 96>>>(vocab, W_lin4, b2, out);
}

// round 8
// speedup vs baseline: 2.6619x; 1.4359x over previous
#include <cuda_runtime.h>
#include <cuda_fp16.h>
#include <math.h>

#define NN 100000
#define EE 1000000
#define EMBD 30

// ---------------- scratch (static device memory; no allocs) ----------------
__device__ float4 g_f4[NN];           // (f0, f1, f2, el1) per node
__device__ float  g_er1[NN];
__device__ __half g_z2h[NN * 32];     // 30 used + 2 zero pad, fp16
__device__ float  g_el2[NN], g_er2[NN];
__device__ float  g_himg[EMBD];
__device__ float  g_wa1[3], g_wr1[3];
__device__ float  g_wa2[64], g_wr2[64];
__device__ float  g_W2T[EMBD * 64];   // W2T[j*64+k] = W2[k*60+j]
__device__ float  g_acc[32];

// CSR build scratch
__device__ int g_count[NN];
__device__ int g_start[NN + 1];
__device__ int g_cursor[NN];
__device__ int g_bsum[256];
__device__ int g_boff[256];
__device__ int g_srcs[EE];            // src node id per dst-sorted edge

// ---------------- K0: tiny prep ----------------
__global__ void k0_prep(const float* __restrict__ x, const float* __restrict__ W_lin1,
                        const float* __restrict__ w_conv2, const float* __restrict__ w_conv3,
                        const float* __restrict__ W1, const float* __restrict__ al1,
                        const float* __restrict__ ar1,
                        const float* __restrict__ W2, const float* __restrict__ al2,
                        const float* __restrict__ ar2)
{
    __shared__ float s_hi[EMBD];
    int t = threadIdx.x;  // 128 threads
    if (t < EMBD) {
        float acc = 0.f;
        const float* row = W_lin1 + t * 512;
        for (int k = 0; k < 512; k++) acc += row[k] * x[k];
        s_hi[t] = acc;
    }
    __syncthreads();
    if (t < EMBD) {
        float hi = s_hi[t];
        float acc = 0.f;
        for (int k = 0; k < 64; k++) {
            float s = 1.f / (1.f + __expf(-w_conv2[k] * hi));
            acc += w_conv3[k] * s;
        }
        g_himg[t] = 1.f / (1.f + __expf(-acc));
    }
    if (t < 3) {
        float a = 0.f, r = 0.f;
        for (int j = 0; j < 64; j++) { a += W1[t * 128 + j] * al1[j]; r += W1[t * 128 + j] * ar1[j]; }
        g_wa1[t] = a; g_wr1[t] = r;
    }
    if (t >= 64 && t < 128) {
        int k = t - 64;
        float a = 0.f, r = 0.f;
        for (int j = 0; j < EMBD; j++) { a += W2[k * 60 + j] * al2[j]; r += W2[k * 60 + j] * ar2[j]; }
        g_wa2[k] = a; g_wr2[k] = r;
    }
    for (int idx = t; idx < EMBD * 64; idx += 128) {
        int j = idx >> 6, k = idx & 63;
        g_W2T[idx] = W2[k * 60 + j];
    }
    if (t < 32) g_acc[t] = 0.f;
}

// ---------------- K1: per-node f4/el1/er1 + zero histogram ----------------
__global__ void k1_nodes1(const float* __restrict__ feat)
{
    int n = blockIdx.x * blockDim.x + threadIdx.x;
    if (n >= NN) return;
    float f0 = feat[n * 3 + 0], f1 = feat[n * 3 + 1], f2 = feat[n * 3 + 2];
    float el = f0 * g_wa1[0] + f1 * g_wa1[1] + f2 * g_wa1[2];
    g_f4[n]  = make_float4(f0, f1, f2, el);
    g_er1[n] = f0 * g_wr1[0] + f1 * g_wr1[1] + f2 * g_wr1[2];
    g_count[n] = 0;
}

// ---------------- CSR build ----------------
__global__ void kh_hist(const int* __restrict__ dst)
{
    int i = blockIdx.x * blockDim.x + threadIdx.x;
    if (i >= EE) return;
    atomicAdd(&g_count[dst[i]], 1);
}

// shfl-based block exclusive scan, 512 elems per block
__global__ void ks1_scan(void)
{
    __shared__ int ws[16];
    int t = threadIdx.x, lane = t & 31, w = t >> 5;
    int i = blockIdx.x * 512 + t;
    int v = (i < NN) ? g_count[i] : 0;
    int x = v;
#pragma unroll
    for (int off = 1; off < 32; off <<= 1) {
        int u = __shfl_up_sync(0xffffffffu, x, off);
        if (lane >= off) x += u;
    }
    if (lane == 31) ws[w] = x;
    __syncthreads();
    if (w == 0) {
        int y = (lane < 16) ? ws[lane] : 0;
#pragma unroll
        for (int off = 1; off < 16; off <<= 1) {
            int u = __shfl_up_sync(0xffffffffu, y, off);
            if (lane >= off) y += u;
        }
        if (lane < 16) ws[lane] = y;
    }
    __syncthreads();
    int incl = x + (w > 0 ? ws[w - 1] : 0);
    if (i < NN) g_start[i] = incl - v;
    if (t == 511) g_bsum[blockIdx.x] = incl;
}

__global__ void ks2_scan(void)   // 1 block, 256 threads, 196 valid block sums
{
    __shared__ int ws[8];
    int t = threadIdx.x, lane = t & 31, w = t >> 5;
    int v = (t < 196) ? g_bsum[t] : 0;
    int x = v;
#pragma unroll
    for (int off = 1; off < 32; off <<= 1) {
        int u = __shfl_up_sync(0xffffffffu, x, off);
        if (lane >= off) x += u;
    }
    if (lane == 31) ws[w] = x;
    __syncthreads();
    if (w == 0) {
        int y = (lane < 8) ? ws[lane] : 0;
#pragma unroll
        for (int off = 1; off < 8; off <<= 1) {
            int u = __shfl_up_sync(0xffffffffu, y, off);
            if (lane >= off) y += u;
        }
        if (lane < 8) ws[lane] = y;
    }
    __syncthreads();
    int incl = x + (w > 0 ? ws[w - 1] : 0);
    if (t < 196) g_boff[t] = incl - v;
}

__global__ void ks3_apply(void)
{
    int i = blockIdx.x * blockDim.x + threadIdx.x;
    if (i < NN) {
        int st = g_start[i] + g_boff[i >> 9];
        g_start[i] = st;
        g_cursor[i] = st;
    }
    if (i == NN) g_start[NN] = EE;
}

// scatter: src-id only
__global__ void kd_scatter(const int* __restrict__ src, const int* __restrict__ dst)
{
    int i = blockIdx.x * blockDim.x + threadIdx.x;
    if (i >= EE) return;
    int d = dst[i];
    int pos = atomicAdd(&g_cursor[d], 1);
    g_srcs[pos] = src[i];
}

// ---------------- K45: FUSED layer-1 aggregation + relu/bias + 64->30 GEMM ----------------
// thread per node: aggregate 3-dim feature (rank-3 trick), expand via W1 head0.
__global__ void __launch_bounds__(256) k45_nodes(const float* __restrict__ W1,
                                                 const float* __restrict__ b1)
{
    __shared__ float sW1[3 * 64];
    __shared__ float sb1[64];
    __shared__ float sW[EMBD * 64 + 2 * 64];
    for (int idx = threadIdx.x; idx < 3 * 64; idx += blockDim.x) {
        int i = idx >> 6, k = idx & 63;
        sW1[idx] = W1[i * 128 + k];
    }
    for (int idx = threadIdx.x; idx < 64; idx += blockDim.x) sb1[idx] = b1[idx];
    for (int idx = threadIdx.x; idx < EMBD * 64; idx += blockDim.x) sW[idx] = g_W2T[idx];
    for (int idx = threadIdx.x; idx < 64; idx += blockDim.x) {
        sW[EMBD * 64 + idx] = g_wa2[idx];
        sW[EMBD * 64 + 64 + idx] = g_wr2[idx];
    }
    __syncthreads();

    int n = blockIdx.x * blockDim.x + threadIdx.x;
    if (n >= NN) return;

    int rs = g_start[n], re = g_start[n + 1];
    float ern = g_er1[n];

    // aggregate p-weighted 3-vector + denominator over this node's edges
    float a0 = 0.f, a1 = 0.f, a2 = 0.f, den = 0.f;
#pragma unroll 2
    for (int e = rs; e < re; e++) {
        int s = g_srcs[e];
        float4 f = g_f4[s];
        float v = f.w + ern;
        v = v > 0.f ? v : 0.2f * v;
        float p = __expf(v);
        den += p;
        a0 = fmaf(p, f.x, a0);
        a1 = fmaf(p, f.y, a1);
        a2 = fmaf(p, f.z, a2);
    }
    float inv = (re > rs) ? (1.f / den) : 0.f;
    a0 *= inv; a1 *= inv; a2 *= inv;

    // r1 = relu(agg3 @ W1h0 + b1); z2 = r1 @ W2T; el2/er2
    float acc[EMBD];
#pragma unroll
    for (int j = 0; j < EMBD; j++) acc[j] = 0.f;
    float el = 0.f, er = 0.f;

#pragma unroll
    for (int kc = 0; kc < 64; kc += 8) {
        float r[8];
#pragma unroll
        for (int u = 0; u < 8; u++) {
            float v = a0 * sW1[kc + u] + a1 * sW1[64 + kc + u] + a2 * sW1[128 + kc + u]
                    + sb1[kc + u];
            r[u] = v > 0.f ? v : 0.f;
        }
#pragma unroll
        for (int j = 0; j < EMBD; j++) {
#pragma unroll
            for (int u = 0; u < 8; u++)
                acc[j] += r[u] * sW[j * 64 + kc + u];
        }
#pragma unroll
        for (int u = 0; u < 8; u++) {
            el += r[u] * sW[EMBD * 64 + kc + u];
            er += r[u] * sW[EMBD * 64 + 64 + kc + u];
        }
    }
    // pack 30 halves + 2 zero pads as 4x uint4
    union { __half2 h[16]; uint4 u4[4]; } pk;
#pragma unroll
    for (int j = 0; j < 15; j++) pk.h[j] = __floats2half2_rn(acc[2 * j], acc[2 * j + 1]);
    pk.h[15] = __floats2half2_rn(0.f, 0.f);
#pragma unroll
    for (int u = 0; u < 4; u++)
        *(uint4*)&g_z2h[n * 32 + u * 8] = pk.u4[u];
    g_el2[n] = el; g_er2[n] = er;
}

// ---------------- K6: layer-2 aggregation + block-level mean accumulation ----------------
__global__ void __launch_bounds__(256) k6_agg2(void)
{
    __shared__ float sacc[32];
    if (threadIdx.x < 32) sacc[threadIdx.x] = 0.f;
    __syncthreads();

    int warp = (blockIdx.x * 256 + threadIdx.x) >> 5;
    int lane = threadIdx.x & 31;
    int rs = 0, re = 0;
    float ern = 0.f;
    if (warp < NN) {
        rs = g_start[warp]; re = g_start[warp + 1];
        ern = g_er2[warp];
    }

    float a0 = 0.f;
    int deg = re - rs;
    if (deg > 0 && deg <= 32) {
        // fast path: single pass, p computed once per edge
        int   s_l = 0;
        float p_l = 0.f;
        if (lane < deg) {
            s_l = g_srcs[rs + lane];
            float v = g_el2[s_l] + ern;
            v = v > 0.f ? v : 0.2f * v;
            p_l = __expf(v);
        }
        float den = p_l;
#pragma unroll
        for (int o = 16; o > 0; o >>= 1) den += __shfl_xor_sync(0xffffffffu, den, o);
        float inv = 1.f / den;
        for (int j = 0; j < deg; j++) {
            int   s     = __shfl_sync(0xffffffffu, s_l, j);
            float alpha = __shfl_sync(0xffffffffu, p_l, j) * inv;
            a0 = fmaf(alpha, __half2float(g_z2h[s * 32 + lane]), a0);
        }
    } else if (deg > 32) {
        float den = 0.f;
        for (int e = rs + lane; e < re; e += 32) {
            int s = g_srcs[e];
            float v = g_el2[s] + ern;
            v = v > 0.f ? v : 0.2f * v;
            den += __expf(v);
        }
#pragma unroll
        for (int o = 16; o > 0; o >>= 1) den += __shfl_xor_sync(0xffffffffu, den, o);
        float inv = 1.f / den;
        for (int base = rs; base < re; base += 32) {
            int m = re - base; if (m > 32) m = 32;
            int   s_l = 0;
            float p_l = 0.f;
            if (lane < m) {
                s_l = g_srcs[base + lane];
                float v = g_el2[s_l] + ern;
                v = v > 0.f ? v : 0.2f * v;
                p_l = __expf(v);
            }
            for (int j = 0; j < m; j++) {
                int   s     = __shfl_sync(0xffffffffu, s_l, j);
                float alpha = __shfl_sync(0xffffffffu, p_l, j) * inv;
                a0 = fmaf(alpha, __half2float(g_z2h[s * 32 + lane]), a0);
            }
        }
    }

    // block-level accumulation of node sums (mean over nodes is all we need)
    atomicAdd(&sacc[lane], a0);
    __syncthreads();
    if (threadIdx.x < 30)
        atomicAdd(&g_acc[threadIdx.x], sacc[threadIdx.x]);
}

// ---------------- K8: concat + linear + log_softmax ----------------
__global__ void k8_final(const float* __restrict__ vocab, const float* __restrict__ W_lin4,
                         const float* __restrict__ b2, float* __restrict__ out)
{
    __shared__ float h[70];
    __shared__ float l[2];
    int t = threadIdx.x;  // 96 threads
    if (t < 30)      h[t] = g_acc[t] * (1.f / (float)NN) + b2[t];
    else if (t < 60) h[t] = g_himg[t - 30];
    else if (t < 70) h[t] = vocab[t - 60];
    __syncthreads();
    if (t < 2) {
        float acc = 0.f;
        for (int k = 0; k < 70; k++) acc += W_lin4[t * 70 + k] * h[k];
        l[t] = acc;
    }
    __syncthreads();
    if (t < 2) {
        float m = fmaxf(l[0], l[1]);
        float lse = m + logf(expf(l[0] - m) + expf(l[1] - m));
        out[t] = l[t] - lse;
    }
}

// ---------------- launch ----------------
extern "C" void kernel_launch(void* const* d_in, const int* in_sizes, int n_in,
                              void* d_out, int out_size)
{
    const float* x       = (const float*)d_in[0];
    const float* feat    = (const float*)d_in[1];
    const float* vocab   = (const float*)d_in[2];
    const int*   src     = (const int*)d_in[3];
    const int*   dst     = (const int*)d_in[4];
    const float* W_lin1  = (const float*)d_in[5];
    const float* w_conv2 = (const float*)d_in[6];
    const float* w_conv3 = (const float*)d_in[7];
    const float* W_lin4  = (const float*)d_in[8];
    const float* W1      = (const float*)d_in[9];
    const float* al1     = (const float*)d_in[10];
    const float* ar1     = (const float*)d_in[11];
    const float* b1      = (const float*)d_in[12];
    const float* W2      = (const float*)d_in[13];
    const float* al2     = (const float*)d_in[14];
    const float* ar2     = (const float*)d_in[15];
    const float* b2      = (const float*)d_in[16];
    float* out = (float*)d_out;

    k0_prep<<<1, 128>>>(x, W_lin1, w_conv2, w_conv3, W1, al1, ar1, W2, al2, ar2);
    k1_nodes1<<<(NN + 255) / 256, 256>>>(feat);
    kh_hist<<<(EE + 255) / 256, 256>>>(dst);
    ks1_scan<<<196, 512>>>();
    ks2_scan<<<1, 256>>>();
    ks3_apply<<<(NN + 1 + 255) / 256, 256>>>();
    kd_scatter<<<(EE + 255) / 256, 256>>>(src, dst);
    k45_nodes<<<(NN + 255) / 256, 256>>>(W1, b1);
    k6_agg2<<<(NN * 32 + 255) / 256, 256>>>();
    k8_final<<<1, 96>>>(vocab, W_lin4, b2, out);
}

// round 11
// speedup vs baseline: 3.5871x; 1.3475x over previous
#include <cuda_runtime.h>
#include <cuda_fp16.h>
#include <math.h>

#define NN 100000
#define EE 1000000
#define EMBD 30

// ---------------- scratch (static device memory; no allocs) ----------------
__device__ float4 g_f4[NN];          // (f0, f1, f2, el1) per node
__device__ float  g_er1[NN];
__device__ float4 g_agg4[NN];        // per-dst (Σp·f0, Σp·f1, Σp·f2, Σp)
__device__ __half g_r1h[NN * 64];    // layer-1 output (head 0), fp16
__device__ float  g_el2[NN], g_er2[NN], g_den2[NN], g_w[NN];
__device__ float  g_p2[EE];
__device__ float  g_himg[EMBD];
__device__ float  g_wa1[3], g_wr1[3];
__device__ float  g_wa2[64], g_wr2[64];
__device__ float  g_W2T[EMBD * 64];  // W2T[j*64+k] = W2[k*60+j]
__device__ float  g_s64[64];         // Σ_n w[n] * r1[n]

// ---------------- K0: tiny prep ----------------
__global__ void k0_prep(const float* __restrict__ x, const float* __restrict__ W_lin1,
                        const float* __restrict__ w_conv2, const float* __restrict__ w_conv3,
                        const float* __restrict__ W1, const float* __restrict__ al1,
                        const float* __restrict__ ar1,
                        const float* __restrict__ W2, const float* __restrict__ al2,
                        const float* __restrict__ ar2)
{
    __shared__ float s_hi[EMBD];
    int t = threadIdx.x;  // 128 threads
    if (t < EMBD) {
        float acc = 0.f;
        const float* row = W_lin1 + t * 512;
        for (int k = 0; k < 512; k++) acc += row[k] * x[k];
        s_hi[t] = acc;
    }
    __syncthreads();
    if (t < EMBD) {
        float hi = s_hi[t];
        float acc = 0.f;
        for (int k = 0; k < 64; k++) {
            float s = 1.f / (1.f + __expf(-w_conv2[k] * hi));
            acc += w_conv3[k] * s;
        }
        g_himg[t] = 1.f / (1.f + __expf(-acc));
    }
    if (t < 3) {
        float a = 0.f, r = 0.f;
        for (int j = 0; j < 64; j++) { a += W1[t * 128 + j] * al1[j]; r += W1[t * 128 + j] * ar1[j]; }
        g_wa1[t] = a; g_wr1[t] = r;
    }
    if (t >= 64 && t < 128) {
        int k = t - 64;
        float a = 0.f, r = 0.f;
        for (int j = 0; j < EMBD; j++) { a += W2[k * 60 + j] * al2[j]; r += W2[k * 60 + j] * ar2[j]; }
        g_wa2[k] = a; g_wr2[k] = r;
    }
    for (int idx = t; idx < EMBD * 64; idx += 128) {
        int j = idx >> 6, k = idx & 63;
        g_W2T[idx] = W2[k * 60 + j];
    }
    if (t < 64) g_s64[t] = 0.f;
}

// ---------------- K1: per-node f4/el1/er1 + zero accumulators ----------------
__global__ void k1_nodes1(const float* __restrict__ feat)
{
    int n = blockIdx.x * blockDim.x + threadIdx.x;
    if (n >= NN) return;
    float f0 = feat[n * 3 + 0], f1 = feat[n * 3 + 1], f2 = feat[n * 3 + 2];
    float el = f0 * g_wa1[0] + f1 * g_wa1[1] + f2 * g_wa1[2];
    g_f4[n]   = make_float4(f0, f1, f2, el);
    g_er1[n]  = f0 * g_wr1[0] + f1 * g_wr1[1] + f2 * g_wr1[2];
    g_agg4[n] = make_float4(0.f, 0.f, 0.f, 0.f);
    g_den2[n] = 0.f;
    g_w[n]    = 0.f;
}

// ---------------- E1: layer-1 edge pass — one v4 RED per edge ----------------
__global__ void e1_edge(const int* __restrict__ src, const int* __restrict__ dst)
{
    int i = blockIdx.x * blockDim.x + threadIdx.x;
    if (i >= EE) return;
    int s = src[i], d = dst[i];
    float4 f = g_f4[s];
    float v = f.w + g_er1[d];
    v = v > 0.f ? v : 0.2f * v;
    float p = __expf(v);
    asm volatile("red.global.add.v4.f32 [%0], {%1, %2, %3, %4};"
                 :: "l"(&g_agg4[d]), "f"(p * f.x), "f"(p * f.y), "f"(p * f.z), "f"(p)
                 : "memory");
}

// ---------------- K45: per-node expand 3->64, relu, el2/er2, store r1 fp16 ----------------
__global__ void __launch_bounds__(256) k45_nodes(const float* __restrict__ W1,
                                                 const float* __restrict__ b1)
{
    __shared__ float sW1[3 * 64];
    __shared__ float sb1[64], swa[64], swr[64];
    for (int idx = threadIdx.x; idx < 3 * 64; idx += blockDim.x) {
        int i = idx >> 6, k = idx & 63;
        sW1[idx] = W1[i * 128 + k];
    }
    for (int idx = threadIdx.x; idx < 64; idx += blockDim.x) {
        sb1[idx] = b1[idx];
        swa[idx] = g_wa2[idx];
        swr[idx] = g_wr2[idx];
    }
    __syncthreads();

    int n = blockIdx.x * blockDim.x + threadIdx.x;
    if (n >= NN) return;

    float4 a = g_agg4[n];
    float inv = (a.w > 0.f) ? (1.f / a.w) : 0.f;
    float a0 = a.x * inv, a1 = a.y * inv, a2 = a.z * inv;

    float el = 0.f, er = 0.f;
    union { __half2 h[4]; uint4 u4; } pk;
#pragma unroll
    for (int kc = 0; kc < 64; kc += 8) {
        float r[8];
#pragma unroll
        for (int u = 0; u < 8; u++) {
            float v = a0 * sW1[kc + u] + a1 * sW1[64 + kc + u] + a2 * sW1[128 + kc + u]
                    + sb1[kc + u];
            r[u] = v > 0.f ? v : 0.f;
            el += r[u] * swa[kc + u];
            er += r[u] * swr[kc + u];
        }
#pragma unroll
        for (int u = 0; u < 4; u++) pk.h[u] = __floats2half2_rn(r[2 * u], r[2 * u + 1]);
        *(uint4*)&g_r1h[n * 64 + kc] = pk.u4;
    }
    g_el2[n] = el;
    g_er2[n] = er;
}

// ---------------- E2A: layer-2 edge pass A — p2 + den RED ----------------
__global__ void e2a_edge(const int* __restrict__ src, const int* __restrict__ dst)
{
    int i = blockIdx.x * blockDim.x + threadIdx.x;
    if (i >= EE) return;
    int s = src[i], d = dst[i];
    float v = g_el2[s] + g_er2[d];
    v = v > 0.f ? v : 0.2f * v;
    float p = __expf(v);
    g_p2[i] = p;
    atomicAdd(&g_den2[d], p);
}

// ---------------- E2C: layer-2 edge pass B — per-src alpha sum ----------------
__global__ void e2c_edge(const int* __restrict__ src, const int* __restrict__ dst)
{
    int i = blockIdx.x * blockDim.x + threadIdx.x;
    if (i >= EE) return;
    float alpha = g_p2[i] / g_den2[dst[i]];
    atomicAdd(&g_w[src[i]], alpha);
}

// ---------------- K7: S64 = Σ_n w[n]·r1[n]  (coalesced) ----------------
__global__ void __launch_bounds__(256) k7_reduce(void)
{
    __shared__ float sh[64];
    int t = threadIdx.x, lane = t & 31, wrp = t >> 5;
    if (t < 64) sh[t] = 0.f;
    __syncthreads();

    const __half2* r = (const __half2*)g_r1h;
    int gw = blockIdx.x * 8 + wrp;
    int nw = gridDim.x * 8;
    float ax = 0.f, ay = 0.f;
    for (int n = gw; n < NN; n += nw) {
        float wn = g_w[n];
        float2 f = __half22float2(r[n * 32 + lane]);
        ax = fmaf(wn, f.x, ax);
        ay = fmaf(wn, f.y, ay);
    }
    atomicAdd(&sh[2 * lane], ax);
    atomicAdd(&sh[2 * lane + 1], ay);
    __syncthreads();
    if (t < 64) atomicAdd(&g_s64[t], sh[t]);
}

// ---------------- K8: final GEMM(64x30) + concat + linear + log_softmax ----------------
__global__ void k8_final(const float* __restrict__ vocab, const float* __restrict__ W_lin4,
                         const float* __restrict__ b2, float* __restrict__ out)
{
    __shared__ float h[70];
    __shared__ float l[2];
    int t = threadIdx.x;  // 96 threads
    if (t < 30) {
        float acc = 0.f;
        for (int k = 0; k < 64; k++) acc += g_s64[k] * g_W2T[t * 64 + k];
        h[t] = acc * (1.f / (float)NN) + b2[t];
    }
    else if (t < 60) h[t] = g_himg[t - 30];
    else if (t < 70) h[t] = vocab[t - 60];
    __syncthreads();
    if (t < 2) {
        float acc = 0.f;
        for (int k = 0; k < 70; k++) acc += W_lin4[t * 70 + k] * h[k];
        l[t] = acc;
    }
    __syncthreads();
    if (t < 2) {
        float m = fmaxf(l[0], l[1]);
        float lse = m + logf(expf(l[0] - m) + expf(l[1] - m));
        out[t] = l[t] - lse;
    }
}

// ---------------- launch ----------------
extern "C" void kernel_launch(void* const* d_in, const int* in_sizes, int n_in,
                              void* d_out, int out_size)
{
    const float* x       = (const float*)d_in[0];
    const float* feat    = (const float*)d_in[1];
    const float* vocab   = (const float*)d_in[2];
    const int*   src     = (const int*)d_in[3];
    const int*   dst     = (const int*)d_in[4];
    const float* W_lin1  = (const float*)d_in[5];
    const float* w_conv2 = (const float*)d_in[6];
    const float* w_conv3 = (const float*)d_in[7];
    const float* W_lin4  = (const float*)d_in[8];
    const float* W1      = (const float*)d_in[9];
    const float* al1     = (const float*)d_in[10];
    const float* ar1     = (const float*)d_in[11];
    const float* b1      = (const float*)d_in[12];
    const float* W2      = (const float*)d_in[13];
    const float* al2     = (const float*)d_in[14];
    const float* ar2     = (const float*)d_in[15];
    const float* b2      = (const float*)d_in[16];
    float* out = (float*)d_out;

    k0_prep<<<1, 128>>>(x, W_lin1, w_conv2, w_conv3, W1, al1, ar1, W2, al2, ar2);
    k1_nodes1<<<(NN + 255) / 256, 256>>>(feat);
    e1_edge<<<(EE + 255) / 256, 256>>>(src, dst);
    k45_nodes<<<(NN + 255) / 256, 256>>>(W1, b1);
    e2a_edge<<<(EE + 255) / 256, 256>>>(src, dst);
    e2c_edge<<<(EE + 255) / 256, 256>>>(src, dst);
    k7_reduce<<<160, 256>>>();
    k8_final<<<1, 96>>>(vocab, W_lin4, b2, out);
}